// round 1
// baseline (speedup 1.0000x reference)
#include <cuda_runtime.h>
#include <cuda_bf16.h>
#include <cstdint>

#define VOCAB   8192
#define EMB     256
#define NROWS   16384
#define M_TILE  64
#define N_CHUNK 128
#define K_CHUNK 64

// scratch: 0.5 * ||e||^2 per code
__device__ float g_e_half[VOCAB];

// ---------------------------------------------------------------------------
// prep: compute g_e_half and zero the ref_count region of the output
// ---------------------------------------------------------------------------
__global__ void vq_prep_kernel(const float* __restrict__ cb, float* __restrict__ ref_out) {
    int gtid = blockIdx.x * blockDim.x + threadIdx.x;
    int warp = gtid >> 5;
    int lane = threadIdx.x & 31;
    if (warp < VOCAB) {
        const float4* row = (const float4*)(cb + (size_t)warp * EMB); // 64 float4
        float4 a = row[lane];
        float4 b = row[lane + 32];
        float s = a.x*a.x + a.y*a.y + a.z*a.z + a.w*a.w
                + b.x*b.x + b.y*b.y + b.z*b.z + b.w*b.w;
        #pragma unroll
        for (int o = 16; o > 0; o >>= 1) s += __shfl_xor_sync(0xffffffffu, s, o);
        if (lane == 0) g_e_half[warp] = 0.5f * s;
    }
    if (gtid < VOCAB) ref_out[gtid] = 0.0f;
}

// ---------------------------------------------------------------------------
// main fused kernel: GEMM + argmax(score) + token write + zq gather + histogram
// score(r,c) = z_r . e_c - 0.5*||e_c||^2   (argmax score == argmin dist)
// ---------------------------------------------------------------------------
__global__ void __launch_bounds__(256, 2)
vq_main_kernel(const float* __restrict__ z, const float* __restrict__ cb,
               float* __restrict__ tok_out, float* __restrict__ zq_out,
               float* __restrict__ ref_out) {
    extern __shared__ float smem[];
    float* zs = smem;                    // [64][256] rows of z
    float* es = smem + M_TILE * EMB;     // [K_CHUNK][N_CHUNK] k-major code tile

    const int tid = threadIdx.x;
    const int cx  = tid & 31;            // code-slice index 0..31
    const int ry  = tid >> 5;            // row-group 0..7
    const int row0 = blockIdx.x * M_TILE;

    // ---- load all 64 z rows (full K) into smem, float4-coalesced ----
    {
        const float4* src = (const float4*)(z + (size_t)row0 * EMB);
        float4* dst = (float4*)zs;
        #pragma unroll
        for (int p = 0; p < 16; ++p) dst[tid + p * 256] = src[tid + p * 256];
    }

    float best[8];
    int   bidx[8];
    #pragma unroll
    for (int r = 0; r < 8; ++r) { best[r] = -3.4e38f; bidx[r] = 0; }

    #pragma unroll 1
    for (int nc = 0; nc < VOCAB / N_CHUNK; ++nc) {
        float acc[8][4];
        #pragma unroll
        for (int r = 0; r < 8; ++r) {
            acc[r][0] = 0.f; acc[r][1] = 0.f; acc[r][2] = 0.f; acc[r][3] = 0.f;
        }

        #pragma unroll 1
        for (int kc = 0; kc < EMB / K_CHUNK; ++kc) {
            __syncthreads();   // protect es from previous iteration's readers
            // stage es[k][c] (k-major) for codes [nc*128, nc*128+128), k in [kc*64, kc*64+64)
            {
                const int c  = tid & 127;
                const int kg = tid >> 7;   // 0..1
                const float* src = cb + (size_t)(nc * N_CHUNK + c) * EMB + kc * K_CHUNK;
                #pragma unroll
                for (int g = 0; g < 8; ++g) {
                    const int k4 = kg * 8 + g;     // 0..15
                    float4 v = *(const float4*)(src + k4 * 4);
                    es[(k4 * 4 + 0) * N_CHUNK + c] = v.x;
                    es[(k4 * 4 + 1) * N_CHUNK + c] = v.y;
                    es[(k4 * 4 + 2) * N_CHUNK + c] = v.z;
                    es[(k4 * 4 + 3) * N_CHUNK + c] = v.w;
                }
            }
            __syncthreads();

            // compute: 8 rows x 4 codes per thread over 64 k
            #pragma unroll
            for (int k4 = 0; k4 < K_CHUNK / 4; ++k4) {
                const float4 e0 = *(const float4*)&es[(k4 * 4 + 0) * N_CHUNK + cx * 4];
                const float4 e1 = *(const float4*)&es[(k4 * 4 + 1) * N_CHUNK + cx * 4];
                const float4 e2 = *(const float4*)&es[(k4 * 4 + 2) * N_CHUNK + cx * 4];
                const float4 e3 = *(const float4*)&es[(k4 * 4 + 3) * N_CHUNK + cx * 4];
                #pragma unroll
                for (int r = 0; r < 8; ++r) {
                    const float4 zv = *(const float4*)&zs[(ry * 8 + r) * EMB + kc * K_CHUNK + k4 * 4];
                    acc[r][0] += zv.x * e0.x; acc[r][1] += zv.x * e0.y;
                    acc[r][2] += zv.x * e0.z; acc[r][3] += zv.x * e0.w;
                    acc[r][0] += zv.y * e1.x; acc[r][1] += zv.y * e1.y;
                    acc[r][2] += zv.y * e1.z; acc[r][3] += zv.y * e1.w;
                    acc[r][0] += zv.z * e2.x; acc[r][1] += zv.z * e2.y;
                    acc[r][2] += zv.z * e2.z; acc[r][3] += zv.z * e2.w;
                    acc[r][0] += zv.w * e3.x; acc[r][1] += zv.w * e3.y;
                    acc[r][2] += zv.w * e3.z; acc[r][3] += zv.w * e3.w;
                }
            }
        }

        // fold in -0.5||e||^2 and update running argmax (ascending code order
        // + strict '>' keeps the FIRST index on ties, matching argmin)
        const int cbase = nc * N_CHUNK + cx * 4;
        const float4 eh = *(const float4*)&g_e_half[cbase];
        #pragma unroll
        for (int r = 0; r < 8; ++r) {
            float s0 = acc[r][0] - eh.x;
            float s1 = acc[r][1] - eh.y;
            float s2 = acc[r][2] - eh.z;
            float s3 = acc[r][3] - eh.w;
            if (s0 > best[r]) { best[r] = s0; bidx[r] = cbase + 0; }
            if (s1 > best[r]) { best[r] = s1; bidx[r] = cbase + 1; }
            if (s2 > best[r]) { best[r] = s2; bidx[r] = cbase + 2; }
            if (s3 > best[r]) { best[r] = s3; bidx[r] = cbase + 3; }
        }
    }

    // ---- cross-thread argmax reduction (reuse es region) ----
    __syncthreads();
    float* redb = es;                        // [64][32] floats
    int*   redi = (int*)(es + M_TILE * 32);  // [64][32] ints
    #pragma unroll
    for (int r = 0; r < 8; ++r) {
        redb[(ry * 8 + r) * 32 + cx] = best[r];
        redi[(ry * 8 + r) * 32 + cx] = bidx[r];
    }
    __syncthreads();

    __shared__ int tok_s[M_TILE];
    if (tid < M_TILE) {
        float b = -3.4e38f;
        int   bi = 0x7fffffff;
        #pragma unroll 4
        for (int i = 0; i < 32; ++i) {
            float v  = redb[tid * 32 + i];
            int   id = redi[tid * 32 + i];
            if (v > b || (v == b && id < bi)) { b = v; bi = id; }
        }
        tok_s[tid] = bi;
        tok_out[row0 + tid] = (float)bi;
        atomicAdd(&ref_out[bi], 1.0f);       // integer-valued fp32 adds: exact, order-free
    }
    __syncthreads();

    // ---- gather z_q rows from the (L2-resident) codebook ----
    {
        float4* dst = (float4*)(zq_out + (size_t)row0 * EMB);
        #pragma unroll
        for (int p = 0; p < 16; ++p) {
            int idx = tid + p * 256;          // 0..4095 float4s
            int r = idx >> 6;                 // row within tile
            int f = idx & 63;                 // float4 within row
            dst[idx] = ((const float4*)(cb + (size_t)tok_s[r] * EMB))[f];
        }
    }
}

// ---------------------------------------------------------------------------
// launch
// ---------------------------------------------------------------------------
extern "C" void kernel_launch(void* const* d_in, const int* in_sizes, int n_in,
                              void* d_out, int out_size) {
    // Identify inputs by element count (robust to ordering).
    const float* z;
    const float* cb;
    if (in_sizes[0] == NROWS * EMB) { z = (const float*)d_in[0]; cb = (const float*)d_in[1]; }
    else                            { z = (const float*)d_in[1]; cb = (const float*)d_in[0]; }

    float* out = (float*)d_out;
    float* tok = out;                              // [NROWS]   tokens (as float)
    float* zq  = out + NROWS;                      // [NROWS*EMB]
    float* ref = out + NROWS + (size_t)NROWS * EMB; // [VOCAB]

    const int smem_bytes = (M_TILE * EMB + K_CHUNK * N_CHUNK) * (int)sizeof(float); // 96 KB
    cudaFuncSetAttribute(vq_main_kernel, cudaFuncAttributeMaxDynamicSharedMemorySize, smem_bytes);

    vq_prep_kernel<<<(VOCAB * 32) / 256, 256>>>(cb, ref);
    vq_main_kernel<<<NROWS / M_TILE, 256, smem_bytes>>>(z, cb, tok, zq, ref);
}

// round 4
// speedup vs baseline: 7.9443x; 7.9443x over previous
#include <cuda_runtime.h>
#include <cuda_bf16.h>
#include <cstdint>

#define VOCAB   8192
#define EMB     256
#define NROWS   16384

// ---------------- global scratch ----------------
__device__ float g_e_half[VOCAB];
__device__ __align__(128) __nv_bfloat16 g_zb[(size_t)NROWS * EMB];
__device__ __align__(128) __nv_bfloat16 g_eb[(size_t)VOCAB * EMB];
__device__ int g_cand[NROWS * 4];

__device__ __forceinline__ uint32_t smem_u32(const void* p) {
    uint32_t a;
    asm("{ .reg .u64 t; cvta.to.shared.u64 t, %1; cvt.u32.u64 %0, t; }" : "=r"(a) : "l"(p));
    return a;
}
__device__ __forceinline__ void cp16(uint32_t dst, const void* src) {
    asm volatile("cp.async.cg.shared.global [%0], [%1], 16;" :: "r"(dst), "l"(src) : "memory");
}

#define MMA16816(c, a, bv0, bv1) \
    asm volatile("mma.sync.aligned.m16n8k16.row.col.f32.bf16.bf16.f32 " \
        "{%0,%1,%2,%3}, {%4,%5,%6,%7}, {%8,%9}, {%0,%1,%2,%3};" \
        : "+f"((c)[0]), "+f"((c)[1]), "+f"((c)[2]), "+f"((c)[3]) \
        : "r"((a)[0]), "r"((a)[1]), "r"((a)[2]), "r"((a)[3]), "r"(bv0), "r"(bv1))

#define LDMX4(r, addr) \
    asm volatile("ldmatrix.sync.aligned.m8n8.x4.shared.b16 {%0,%1,%2,%3}, [%4];" \
        : "=r"((r)[0]), "=r"((r)[1]), "=r"((r)[2]), "=r"((r)[3]) : "r"(addr))

// ---------------- prep kernels ----------------
__device__ __forceinline__ uint32_t pack_bf2(float a, float b) {
    __nv_bfloat162 h = __floats2bfloat162_rn(a, b);
    return *(uint32_t*)&h;
}

__global__ void vq_convert_kernel(const float* __restrict__ z, const float* __restrict__ cb) {
    const int NZ4 = NROWS * EMB / 4;
    const int NE4 = VOCAB * EMB / 4;
    int i = blockIdx.x * blockDim.x + threadIdx.x;
    if (i < NZ4) {
        float4 v = ((const float4*)z)[i];
        ((uint2*)g_zb)[i] = make_uint2(pack_bf2(v.x, v.y), pack_bf2(v.z, v.w));
    } else if (i < NZ4 + NE4) {
        int j = i - NZ4;
        float4 v = ((const float4*)cb)[j];
        ((uint2*)g_eb)[j] = make_uint2(pack_bf2(v.x, v.y), pack_bf2(v.z, v.w));
    }
}

__global__ void vq_prep_kernel(const float* __restrict__ cb, float* __restrict__ ref_out) {
    int gtid = blockIdx.x * blockDim.x + threadIdx.x;
    int warp = gtid >> 5;
    int lane = threadIdx.x & 31;
    if (warp < VOCAB) {
        const float4* row = (const float4*)(cb + (size_t)warp * EMB);
        float4 a = row[lane];
        float4 b = row[lane + 32];
        float s = a.x*a.x + a.y*a.y + a.z*a.z + a.w*a.w
                + b.x*b.x + b.y*b.y + b.z*b.z + b.w*b.w;
        #pragma unroll
        for (int o = 16; o > 0; o >>= 1) s += __shfl_xor_sync(0xffffffffu, s, o);
        if (lane == 0) g_e_half[warp] = 0.5f * s;
    }
    if (gtid < VOCAB) ref_out[gtid] = 0.0f;
}

// ---------------- phase 1: HMMA GEMM + top-candidate select ----------------
#define GCH     32                      // codes per chunk
#define NCHUNKS (VOCAB / GCH)           // 256
#define BBUF    16384                   // bytes per B stage (32 codes x 512B)
#define SM_EH   49152                   // after 3 B stages
#define SMEM_GB (SM_EH + VOCAB * 4)     // 81920

#define TOP2(s_, c_, v1, i1, v2, i2) { float _t = (s_); \
    if (_t > (v2)) { if (_t > (v1)) { (v2)=(v1); (i2)=(i1); (v1)=_t; (i1)=(c_); } \
                     else          { (v2)=_t;  (i2)=(c_); } } }

#define INS4(s_, c_) { float _u = (s_); int _d = (c_); \
    if (_u > w3) { \
        if (_u > w1) { \
            if (_u > w0) { w3=w2;q3=q2; w2=w1;q2=q1; w1=w0;q1=q0; w0=_u;q0=_d; } \
            else         { w3=w2;q3=q2; w2=w1;q2=q1; w1=_u;q1=_d; } \
        } else { \
            if (_u > w2) { w3=w2;q3=q2; w2=_u;q2=_d; } \
            else         { w3=_u;q3=_d; } \
        } } }

__global__ void __launch_bounds__(128, 1) vq_gemm_kernel() {
    extern __shared__ char sm[];
    const uint32_t sb = smem_u32(sm);
    const int tid  = threadIdx.x;
    const int lane = tid & 31;
    const int warp = tid >> 5;
    const int blk  = blockIdx.x;

    // ---- stage this CTA's 128 z rows (512B each) swizzled into smem ----
    {
        const char* src = (const char*)g_zb + (size_t)blk * 128 * 512;
        #pragma unroll
        for (int j = 0; j < 32; ++j) {
            int u = tid + j * 128;
            int n = u >> 5, g = u & 31;
            cp16(sb + n * 512 + ((g ^ (n & 7)) << 4), src + (size_t)u * 16);
        }
        asm volatile("cp.async.commit_group;" ::: "memory");
        asm volatile("cp.async.wait_group 0;" ::: "memory");
        __syncthreads();
    }

    // ---- build resident A fragments: 2 m-blocks x 16 k-blocks x 4 regs ----
    uint32_t A[2][16][4];
    {
        #pragma unroll
        for (int mb = 0; mb < 2; ++mb) {
            const int r = warp * 32 + mb * 16 + (lane & 8) + (lane & 7);
            #pragma unroll
            for (int kb = 0; kb < 16; ++kb) {
                uint32_t addr = sb + r * 512 + (((2 * kb + (lane >> 4)) ^ (lane & 7)) << 4);
                LDMX4(A[mb][kb], addr);
            }
        }
    }
    __syncthreads();   // everyone done reading z staging; smem reusable

    // ---- prologue: first two B chunks + e_half table ----
    {
        const char* src0 = (const char*)g_eb;
        #pragma unroll
        for (int s = 0; s < 2; ++s) {
            const char* src = src0 + (size_t)s * GCH * 512;
            uint32_t dstb = sb + s * BBUF;
            #pragma unroll
            for (int j = 0; j < 8; ++j) {
                int u = tid + j * 128;
                int n = u >> 5, g = u & 31;
                cp16(dstb + n * 512 + ((g ^ (n & 7)) << 4), src + (size_t)u * 16);
            }
            asm volatile("cp.async.commit_group;" ::: "memory");
        }
        for (int i = tid; i < VOCAB; i += 128)
            *(float*)(sm + SM_EH + i * 4) = g_e_half[i];
    }

    float acc[2][4][4];
    #pragma unroll
    for (int mb = 0; mb < 2; ++mb)
        #pragma unroll
        for (int nb = 0; nb < 4; ++nb)
            #pragma unroll
            for (int q = 0; q < 4; ++q) acc[mb][nb][q] = 0.f;

    float tv1[4], tv2[4];
    int   ti1[4], ti2[4];
    #pragma unroll
    for (int s = 0; s < 4; ++s) { tv1[s] = -3.4e38f; tv2[s] = -3.4e38f; ti1[s] = 0; ti2[s] = 0; }

    // per-thread B ldmatrix address pieces
    const int nbase = ((lane >> 4) & 1) * 8 + (lane & 7);
    const uint32_t brow0 = (uint32_t)nbase * 512;
    const uint32_t brow1 = (uint32_t)(nbase + 16) * 512;
    const int gb = (lane >> 3) & 1;
    const int sw = lane & 7;

    for (int ch = 0; ch < NCHUNKS; ++ch) {
        if (ch >= NCHUNKS - 1) asm volatile("cp.async.wait_group 0;" ::: "memory");
        else                   asm volatile("cp.async.wait_group 1;" ::: "memory");
        __syncthreads();

        const uint32_t bb = sb + (uint32_t)(ch % 3) * BBUF;

        #pragma unroll
        for (int kb = 0; kb < 16; ++kb) {
            uint32_t b0r[4], b1r[4];
            const uint32_t go = (uint32_t)(((2 * kb + gb) ^ sw) << 4);
            LDMX4(b0r, bb + brow0 + go);   // n-blocks 0,1
            LDMX4(b1r, bb + brow1 + go);   // n-blocks 2,3
            #pragma unroll
            for (int mb = 0; mb < 2; ++mb) {
                MMA16816(acc[mb][0], A[mb][kb], b0r[0], b0r[1]);
                MMA16816(acc[mb][1], A[mb][kb], b0r[2], b0r[3]);
                MMA16816(acc[mb][2], A[mb][kb], b1r[0], b1r[1]);
                MMA16816(acc[mb][3], A[mb][kb], b1r[2], b1r[3]);
            }
        }

        // epilogue: fold -0.5||e||^2, update per-row top-2, reset acc
        const int c0 = ch * GCH + 2 * (lane & 3);
        #pragma unroll
        for (int nb = 0; nb < 4; ++nb) {
            const int ca = c0 + nb * 8;
            const float2 eh = *(const float2*)(sm + SM_EH + (size_t)ca * 4);
            #pragma unroll
            for (int mb = 0; mb < 2; ++mb) {
                const int s0 = mb * 2, s1 = mb * 2 + 1;
                TOP2(acc[mb][nb][0] - eh.x, ca,     tv1[s0], ti1[s0], tv2[s0], ti2[s0]);
                TOP2(acc[mb][nb][1] - eh.y, ca + 1, tv1[s0], ti1[s0], tv2[s0], ti2[s0]);
                TOP2(acc[mb][nb][2] - eh.x, ca,     tv1[s1], ti1[s1], tv2[s1], ti2[s1]);
                TOP2(acc[mb][nb][3] - eh.y, ca + 1, tv1[s1], ti1[s1], tv2[s1], ti2[s1]);
                acc[mb][nb][0] = 0.f; acc[mb][nb][1] = 0.f;
                acc[mb][nb][2] = 0.f; acc[mb][nb][3] = 0.f;
            }
        }

        // prefetch chunk ch+2
        if (ch + 2 < NCHUNKS) {
            const char* src = (const char*)g_eb + (size_t)(ch + 2) * GCH * 512;
            uint32_t dstb = sb + (uint32_t)((ch + 2) % 3) * BBUF;
            #pragma unroll
            for (int j = 0; j < 8; ++j) {
                int u = tid + j * 128;
                int n = u >> 5, g = u & 31;
                cp16(dstb + n * 512 + ((g ^ (n & 7)) << 4), src + (size_t)u * 16);
            }
            asm volatile("cp.async.commit_group;" ::: "memory");
        }
    }

    // ---- merge per-thread top-2 across the quad -> top-4 per row ----
    #pragma unroll
    for (int slot = 0; slot < 4; ++slot) {
        float w0 = tv1[slot], w1 = tv2[slot], w2 = -3.4e38f, w3 = -3.4e38f;
        int   q0 = ti1[slot], q1 = ti2[slot], q2 = 0, q3 = 0;
        #pragma unroll
        for (int d = 1; d <= 2; d <<= 1) {
            float o0 = __shfl_xor_sync(0xffffffffu, w0, d);
            float o1 = __shfl_xor_sync(0xffffffffu, w1, d);
            float o2 = __shfl_xor_sync(0xffffffffu, w2, d);
            float o3 = __shfl_xor_sync(0xffffffffu, w3, d);
            int   p0 = __shfl_xor_sync(0xffffffffu, q0, d);
            int   p1 = __shfl_xor_sync(0xffffffffu, q1, d);
            int   p2 = __shfl_xor_sync(0xffffffffu, q2, d);
            int   p3 = __shfl_xor_sync(0xffffffffu, q3, d);
            INS4(o0, p0); INS4(o1, p1); INS4(o2, p2); INS4(o3, p3);
        }
        if ((lane & 3) == 0) {
            const int row = blk * 128 + warp * 32 + slot * 8 + (lane >> 2);
            g_cand[row * 4 + 0] = q0;
            g_cand[row * 4 + 1] = q1;
            g_cand[row * 4 + 2] = q2;
            g_cand[row * 4 + 3] = q3;
        }
    }
}

// ---------------- phase 2: exact fp32 rescore + outputs --------------------
__global__ void __launch_bounds__(256) vq_rescore_kernel(
    const float* __restrict__ z, const float* __restrict__ cb,
    float* __restrict__ tok, float* __restrict__ zq, float* __restrict__ ref) {
    const int warp = threadIdx.x >> 5, lane = threadIdx.x & 31;
    const int row  = blockIdx.x * 8 + warp;
    const float4* zr = (const float4*)(z + (size_t)row * EMB);
    const float4 z0 = zr[lane * 2], z1 = zr[lane * 2 + 1];
    float best = -3.4e38f;
    int   bi   = 0x7fffffff;
    #pragma unroll
    for (int k = 0; k < 4; ++k) {
        const int c = g_cand[row * 4 + k];
        const float4* er = (const float4*)(cb + (size_t)c * EMB);
        const float4 e0 = er[lane * 2], e1 = er[lane * 2 + 1];
        float d = z0.x*e0.x + z0.y*e0.y + z0.z*e0.z + z0.w*e0.w
                + z1.x*e1.x + z1.y*e1.y + z1.z*e1.z + z1.w*e1.w;
        #pragma unroll
        for (int o = 16; o > 0; o >>= 1) d += __shfl_xor_sync(0xffffffffu, d, o);
        const float s = d - g_e_half[c];
        if (s > best || (s == best && c < bi)) { best = s; bi = c; }
    }
    tok[row] = (float)bi;
    if (lane == 0) atomicAdd(&ref[bi], 1.0f);
    const float4* eb = (const float4*)(cb + (size_t)bi * EMB);
    float4* o = (float4*)(zq + (size_t)row * EMB);
    o[lane * 2]     = eb[lane * 2];
    o[lane * 2 + 1] = eb[lane * 2 + 1];
}

// ---------------- launch ----------------------------------------------------
extern "C" void kernel_launch(void* const* d_in, const int* in_sizes, int n_in,
                              void* d_out, int out_size) {
    const float* z;
    const float* cb;
    if (in_sizes[0] == NROWS * EMB) { z = (const float*)d_in[0]; cb = (const float*)d_in[1]; }
    else                            { z = (const float*)d_in[1]; cb = (const float*)d_in[0]; }

    float* out = (float*)d_out;
    float* tok = out;
    float* zq  = out + NROWS;
    float* ref = out + NROWS + (size_t)NROWS * EMB;

    cudaFuncSetAttribute(vq_gemm_kernel, cudaFuncAttributeMaxDynamicSharedMemorySize, SMEM_GB);

    const int nconv = (NROWS * EMB / 4) + (VOCAB * EMB / 4);
    vq_convert_kernel<<<(nconv + 255) / 256, 256>>>(z, cb);
    vq_prep_kernel<<<(VOCAB * 32) / 256, 256>>>(cb, ref);
    vq_gemm_kernel<<<NROWS / 128, 128, SMEM_GB>>>();
    vq_rescore_kernel<<<NROWS / 8, 256>>>(z, cb, tok, zq, ref);
}